// round 2
// baseline (speedup 1.0000x reference)
#include <cuda_runtime.h>
#include <cuda_bf16.h>
#include <cstdint>

#define PAIRS 1024
#define DD 256
#define QL 16

// ---------------- persistent scratch / precomputed ----------------
__device__ unsigned g_Mbf[256 * 128];      // A[j][e] as bf16x2 (e pairs)
__device__ float    g_WvT[256 * 256];      // WvT[j][d] = vw_w[d][j]
__device__ float    g_u[256];
__device__ float    g_w[256];
__device__ float    g_c;
__device__ int      g_mask_mode;           // 0=u8 bool, 1=int32, 2=float32
__device__ float    g_tvec[PAIRS * 256];   // attn . v  per pair
__device__ float    g_sA[PAIRS];           // 1 if any unmasked else 0

__device__ __forceinline__ float2 bf2f(unsigned u) {
    float2 r;
    r.x = __uint_as_float(u << 16);
    r.y = __uint_as_float(u & 0xFFFF0000u);
    return r;
}
__device__ __forceinline__ unsigned f2bf(float a, float b) {
    __nv_bfloat162 h = __floats2bfloat162_rn(a, b);
    return *reinterpret_cast<unsigned*>(&h);
}

// ---------------- setup kernel ----------------
__global__ void setup_kernel(const float* __restrict__ qw_w, const float* __restrict__ qw_b,
                             const float* __restrict__ kw_w, const float* __restrict__ kw_b,
                             const float* __restrict__ vw_w, const void* __restrict__ maskp)
{
    const int b = blockIdx.x;
    const int t = threadIdx.x;
    if (b < 256) {
        // A row j = b (bf16 pack) and u[j]
        const int j = b;
        float acc = 0.f;
        #pragma unroll 4
        for (int dd = 0; dd < 256; dd++)
            acc += __ldg(&qw_w[dd * 256 + j]) * kw_w[dd * 256 + t];
        __shared__ float row[256];
        __shared__ float red[8];
        row[t] = acc;
        float up = qw_w[t * 256 + j] * kw_b[t];
        #pragma unroll
        for (int o = 16; o > 0; o >>= 1) up += __shfl_xor_sync(0xffffffffu, up, o);
        if ((t & 31) == 0) red[t >> 5] = up;
        __syncthreads();
        if (t == 0) {
            float s = 0.f;
            #pragma unroll
            for (int i = 0; i < 8; i++) s += red[i];
            g_u[j] = s;
        }
        if (t < 128) g_Mbf[j * 128 + t] = f2bf(row[2 * t], row[2 * t + 1]);
    } else if (b == 256) {
        // w[m=t], c, mask dtype detection
        float acc = 0.f;
        #pragma unroll 4
        for (int dd = 0; dd < 256; dd++)
            acc += kw_w[dd * 256 + t] * __ldg(&qw_b[dd]);
        g_w[t] = acc;
        float cp = qw_b[t] * kw_b[t];
        #pragma unroll
        for (int o = 16; o > 0; o >>= 1) cp += __shfl_xor_sync(0xffffffffu, cp, o);
        __shared__ float redc[8];
        __shared__ int nf[2];
        if ((t & 31) == 0) redc[t >> 5] = cp;
        if (t < 2) nf[t] = 0;
        __syncthreads();
        const unsigned* mw = (const unsigned*)maskp;
        int bad0 = 0, bad1 = 0;
        for (int i = t; i < 16384; i += 256) {   // first 64KB safe in all interps
            unsigned w = mw[i];
            if (w > 1u) bad0 = 1;
            if (w != 0u && w != 0x3F800000u) bad1 = 1;
        }
        if (bad0) nf[0] = 1;
        if (bad1) nf[1] = 1;
        __syncthreads();
        if (t == 0) {
            float s = 0.f;
            #pragma unroll
            for (int i = 0; i < 8; i++) s += redc[i];
            g_c = s;
            g_mask_mode = nf[0] ? (nf[1] ? 0 : 2) : 1;
        }
    } else {
        // WvT transpose: 64 blocks of 32x32 tiles
        __shared__ float s[32][33];
        const int bb = b - 257;
        const int di = (bb >> 3) * 32, jj = (bb & 7) * 32;
        const int tx = t & 31, ty = t >> 5;          // 32 x 8
        #pragma unroll
        for (int u2 = 0; u2 < 4; u2++) {
            int dr = ty + 8 * u2;
            s[dr][tx] = vw_w[(di + dr) * 256 + (jj + tx)];
        }
        __syncthreads();
        #pragma unroll
        for (int u2 = 0; u2 < 4; u2++) {
            int jr = ty + 8 * u2;
            g_WvT[(jj + jr) * 256 + (di + tx)] = s[tx][jr];
        }
    }
}

// ---------------- fused per-pair kernel ----------------
// smem layout (bytes):
//   [0, 66560)         kbf: 128 rows x 130 uints (bf16x2 k tile)  |  qT: 256 x 20 floats (phase 1)
//   [66560, 87168)     QtT: float, row e at e*20 + 8*(e>>6), 16 i's per row
//   [87168, 88192)     wv_s[256]
//   [88192, 88256)     a_s[16]
//   [88256, 89280)     ta_s[256]  (becomes attn)
//   [89280, 89312)     red_s[8]
#define SM_QTT 66560
#define SM_WV  87168
#define SM_A   88192
#define SM_TA  88256
#define SM_RED 89280
#define SM_TOT 89312

__device__ __forceinline__ float bsum(float v, float* red, int t) {
    __syncthreads();
    #pragma unroll
    for (int o = 16; o > 0; o >>= 1) v += __shfl_xor_sync(0xffffffffu, v, o);
    if ((t & 31) == 0) red[t >> 5] = v;
    __syncthreads();
    float r = red[0];
    #pragma unroll
    for (int i = 1; i < 8; i++) r += red[i];
    return r;
}
__device__ __forceinline__ float bmax(float v, float* red, int t) {
    __syncthreads();
    #pragma unroll
    for (int o = 16; o > 0; o >>= 1) v = fmaxf(v, __shfl_xor_sync(0xffffffffu, v, o));
    if ((t & 31) == 0) red[t >> 5] = v;
    __syncthreads();
    float r = red[0];
    #pragma unroll
    for (int i = 1; i < 8; i++) r = fmaxf(r, red[i]);
    return r;
}

__global__ void __launch_bounds__(256, 2)
fused_kernel(const float* __restrict__ q, const float* __restrict__ k,
             const float* __restrict__ v, const void* __restrict__ maskp)
{
    extern __shared__ unsigned char sm[];
    float*    qT    = (float*)sm;
    unsigned* kbf   = (unsigned*)sm;
    float*    QtT   = (float*)(sm + SM_QTT);
    float*    wv_s  = (float*)(sm + SM_WV);
    float*    a_s   = (float*)(sm + SM_A);
    float*    ta_s  = (float*)(sm + SM_TA);
    float*    red_s = (float*)(sm + SM_RED);

    const int pair = blockIdx.x;
    const int t = threadIdx.x;
    const float* qb = q + (size_t)pair * QL * DD;
    const float* kb = k + (size_t)pair * 256 * DD;
    const float* vb = v + (size_t)pair * 256 * DD;

    // ---- stage qT (transposed, stride 20) + w ----
    {
        const float4* qs = (const float4*)qb;   // 1024 float4
        #pragma unroll
        for (int it = 0; it < 4; it++) {
            int idx = it * 256 + t;
            float4 f = qs[idx];
            int i = idx >> 6;
            int d0 = (idx & 63) * 4;
            qT[(d0 + 0) * 20 + i] = f.x;
            qT[(d0 + 1) * 20 + i] = f.y;
            qT[(d0 + 2) * 20 + i] = f.z;
            qT[(d0 + 3) * 20 + i] = f.w;
        }
        wv_s[t] = g_w[t];
    }
    __syncthreads();

    // ---- Phase 1: Qt[i][e] = sum_j q[i][j] * A[j][e] ----
    {
        const int ih = t >> 7;            // i half: 8 i's
        const int ep = t & 127;           // e pair -> e0 = 2*ep
        float acc0[8], acc1[8];
        #pragma unroll
        for (int u = 0; u < 8; u++) { acc0[u] = 0.f; acc1[u] = 0.f; }
        #pragma unroll 4
        for (int d = 0; d < 256; d++) {
            float2 a2 = bf2f(g_Mbf[d * 128 + ep]);
            const float* qr = &qT[d * 20 + ih * 8];
            float4 q0 = *(const float4*)(qr);
            float4 q1 = *(const float4*)(qr + 4);
            acc0[0] += q0.x * a2.x; acc1[0] += q0.x * a2.y;
            acc0[1] += q0.y * a2.x; acc1[1] += q0.y * a2.y;
            acc0[2] += q0.z * a2.x; acc1[2] += q0.z * a2.y;
            acc0[3] += q0.w * a2.x; acc1[3] += q0.w * a2.y;
            acc0[4] += q1.x * a2.x; acc1[4] += q1.x * a2.y;
            acc0[5] += q1.y * a2.x; acc1[5] += q1.y * a2.y;
            acc0[6] += q1.z * a2.x; acc1[6] += q1.z * a2.y;
            acc0[7] += q1.w * a2.x; acc1[7] += q1.w * a2.y;
        }
        const int e0 = 2 * ep;
        const int off = e0 * 20 + ((e0 >> 6) << 3);
        #pragma unroll
        for (int u = 0; u < 8; u++) {
            QtT[off + ih * 8 + u]      = acc0[u];
            QtT[off + 20 + ih * 8 + u] = acc1[u];
        }
    }
    // ---- a_i = q_i . u + c  (warp 0) ----
    if (t < 32) {
        const float cc = g_c;
        for (int i = 0; i < QL; i++) {
            float p = 0.f;
            #pragma unroll
            for (int dd = t; dd < 256; dd += 32)
                p += qT[dd * 20 + i] * g_u[dd];
            #pragma unroll
            for (int o = 16; o > 0; o >>= 1) p += __shfl_xor_sync(0xffffffffu, p, o);
            if (t == 0) a_s[i] = p + cc;
        }
    }

    // ---- Phase 2: scores + row max -> ta, two 128-row tiles ----
    const int qt4 = t & 3;        // e-quarter (lane bits 0-1)
    const int g = t >> 2;         // row pair 0..63
    for (int tile = 0; tile < 2; tile++) {
        __syncthreads();          // kbf region free (qT done / previous tile done)
        {   // stage k tile as bf16, rows [tile*128, tile*128+128)
            const float4* ks = (const float4*)(kb + tile * 128 * 256);
            #pragma unroll 4
            for (int it = 0; it < 32; it++) {
                int idx = it * 256 + t;     // float4 index
                float4 f = ks[idx];
                int row = idx >> 6;
                int c4 = idx & 63;
                uint2 p2 = make_uint2(f2bf(f.x, f.y), f2bf(f.z, f.w));
                *(uint2*)&kbf[row * 130 + 2 * c4] = p2;
            }
        }
        __syncthreads();
        const unsigned* k0p = kbf + (2 * g) * 130;
        const unsigned* k1p = kbf + (2 * g + 1) * 130;
        float acc0[16], acc1[16];
        #pragma unroll
        for (int i = 0; i < 16; i++) { acc0[i] = 0.f; acc1[i] = 0.f; }
        float wk0 = 0.f, wk1 = 0.f;
        const int e2b = qt4 * 32;
        #pragma unroll 4
        for (int j = 0; j < 32; j++) {
            int e2 = e2b + j;
            float2 ka = bf2f(k0p[e2]);
            float2 kc = bf2f(k1p[e2]);
            int e = 2 * e2;
            const float* Q0 = &QtT[e * 20 + 8 * qt4];
            float2 w2 = *(const float2*)&wv_s[e];
            wk0 += w2.x * ka.x + w2.y * ka.y;
            wk1 += w2.x * kc.x + w2.y * kc.y;
            #pragma unroll
            for (int ii = 0; ii < 4; ii++) {
                float4 qa = *(const float4*)(Q0 + 4 * ii);
                float4 qd = *(const float4*)(Q0 + 20 + 4 * ii);
                acc0[4*ii+0] += qa.x * ka.x + qd.x * ka.y;
                acc0[4*ii+1] += qa.y * ka.x + qd.y * ka.y;
                acc0[4*ii+2] += qa.z * ka.x + qd.z * ka.y;
                acc0[4*ii+3] += qa.w * ka.x + qd.w * ka.y;
                acc1[4*ii+0] += qa.x * kc.x + qd.x * kc.y;
                acc1[4*ii+1] += qa.y * kc.x + qd.y * kc.y;
                acc1[4*ii+2] += qa.z * kc.x + qd.z * kc.y;
                acc1[4*ii+3] += qa.w * kc.x + qd.w * kc.y;
            }
        }
        // butterfly across quarters (lane bits 0,1)
        #pragma unroll
        for (int i = 0; i < 16; i++) {
            acc0[i] += __shfl_xor_sync(0xffffffffu, acc0[i], 1);
            acc0[i] += __shfl_xor_sync(0xffffffffu, acc0[i], 2);
            acc1[i] += __shfl_xor_sync(0xffffffffu, acc1[i], 1);
            acc1[i] += __shfl_xor_sync(0xffffffffu, acc1[i], 2);
        }
        wk0 += __shfl_xor_sync(0xffffffffu, wk0, 1);
        wk0 += __shfl_xor_sync(0xffffffffu, wk0, 2);
        wk1 += __shfl_xor_sync(0xffffffffu, wk1, 1);
        wk1 += __shfl_xor_sync(0xffffffffu, wk1, 2);
        if (qt4 == 0) {
            float m0 = -1e30f, m1 = -1e30f;
            #pragma unroll
            for (int i = 0; i < 16; i++) {
                float ai = a_s[i];
                m0 = fmaxf(m0, acc0[i] + ai);
                m1 = fmaxf(m1, acc1[i] + ai);
            }
            ta_s[tile * 128 + 2 * g]     = wk0 + m0;
            ta_s[tile * 128 + 2 * g + 1] = wk1 + m1;
        }
    }

    // ---- Phase 3: normalize, mask, softmax ----
    float tv;
    float cnt;
    {
        __syncthreads();
        tv = ta_s[t];
        float ss = bsum(tv * tv, red_s, t);
        float inv = rsqrtf(ss);
        const int mm = g_mask_mode;
        bool masked;
        size_t mi = (size_t)pair * 256 + t;
        if (mm == 0)      masked = ((const unsigned char*)maskp)[mi] != 0;
        else if (mm == 1) masked = ((const int*)maskp)[mi] != 0;
        else              masked = ((const float*)maskp)[mi] != 0.f;
        float x = masked ? -10.f : tv * inv;
        cnt = bsum(masked ? 0.f : 1.f, red_s, t);
        float mx = bmax(x, red_s, t);
        float ex = __expf(x - mx);
        float se = bsum(ex, red_s, t);
        float attn = (cnt == 0.f) ? 0.f : ex / se;
        ta_s[t] = attn;
        __syncthreads();
    }

    // ---- Phase 4: tvec[j=t] = sum_v attn[v] * v[v][t] ----
    {
        float acc = 0.f;
        #pragma unroll 8
        for (int vv = 0; vv < 256; vv++)
            acc += ta_s[vv] * vb[vv * 256 + t];
        g_tvec[pair * 256 + t] = acc;
        if (t == 0) g_sA[pair] = (cnt > 0.f) ? 1.f : 0.f;
    }
}

// ---------------- output projection: OUT = TVEC @ WvT + sA*vb ----------------
__global__ void out_kernel(const float* __restrict__ vw_b, float* __restrict__ out)
{
    __shared__ float tvT[256 * 20];    // row j: 16 pair-rows, stride 20
    __shared__ float sA_s[16];
    __shared__ float vb_s[256];
    const int t = threadIdx.x;
    const int p0 = blockIdx.x * 16;
    vb_s[t] = vw_b[t];
    if (t < 16) sA_s[t] = g_sA[p0 + t];
    #pragma unroll
    for (int it = 0; it < 16; it++) {
        int idx = it * 256 + t;        // 4096 elems
        int r = idx >> 8, j = idx & 255;
        tvT[j * 20 + r] = g_tvec[(p0 + r) * 256 + j];
    }
    __syncthreads();
    float acc[16];
    #pragma unroll
    for (int r = 0; r < 16; r++) acc[r] = 0.f;
    #pragma unroll 4
    for (int j = 0; j < 256; j++) {
        float wv = g_WvT[j * 256 + t];
        const float4* T = (const float4*)&tvT[j * 20];
        float4 t0 = T[0], t1 = T[1], t2 = T[2], t3 = T[3];
        acc[0]  += t0.x * wv;  acc[1]  += t0.y * wv;
        acc[2]  += t0.z * wv;  acc[3]  += t0.w * wv;
        acc[4]  += t1.x * wv;  acc[5]  += t1.y * wv;
        acc[6]  += t1.z * wv;  acc[7]  += t1.w * wv;
        acc[8]  += t2.x * wv;  acc[9]  += t2.y * wv;
        acc[10] += t2.z * wv;  acc[11] += t2.w * wv;
        acc[12] += t3.x * wv;  acc[13] += t3.y * wv;
        acc[14] += t3.z * wv;  acc[15] += t3.w * wv;
    }
    #pragma unroll
    for (int r = 0; r < 16; r++)
        out[(size_t)(p0 + r) * 256 + t] = acc[r] + sA_s[r] * vb_s[t];
}

extern "C" void kernel_launch(void* const* d_in, const int* in_sizes, int n_in,
                              void* d_out, int out_size)
{
    const float* q    = (const float*)d_in[0];
    const float* k    = (const float*)d_in[1];
    const float* v    = (const float*)d_in[2];
    const void*  m    = d_in[3];
    const float* qw_w = (const float*)d_in[4];
    const float* qw_b = (const float*)d_in[5];
    const float* kw_w = (const float*)d_in[6];
    const float* kw_b = (const float*)d_in[7];
    const float* vw_w = (const float*)d_in[8];
    const float* vw_b = (const float*)d_in[9];
    float* out = (float*)d_out;
    (void)in_sizes; (void)n_in; (void)out_size;

    cudaFuncSetAttribute(fused_kernel, cudaFuncAttributeMaxDynamicSharedMemorySize, SM_TOT);

    setup_kernel<<<321, 256>>>(qw_w, qw_b, kw_w, kw_b, vw_w, m);
    fused_kernel<<<PAIRS, 256, SM_TOT>>>(q, k, v, m);
    out_kernel<<<64, 256>>>(vw_b, out);
}